// round 1
// baseline (speedup 1.0000x reference)
#include <cuda_runtime.h>
#include <math.h>
#include <stdint.h>

#define N_IMG 4608
#define N_TXT 128
#define DIM   4096
#define NB    16384
#define NTH   1024

// ---- scratch (no allocations allowed) ----
__device__ float g_v[DIM];
__device__ float g_invn[N_TXT];
__device__ float g_sim[N_IMG];
__device__ unsigned char g_keep[N_IMG];

// ---------------------------------------------------------------------------
// Kernel 1a: per-text-row inverse norm, masked. Also probes whether the bool
// mask is stored as 1 byte/elem or int32/elem (little-endian): an int32 bool
// array has zero bytes at offsets j with j%4!=0.
// ---------------------------------------------------------------------------
__global__ void k_textnorm(const float* __restrict__ emb,
                           const unsigned char* __restrict__ maskb) {
    int t = blockIdx.x;
    const float* row = emb + (size_t)t * DIM;
    float ss = 0.f;
    for (int d = threadIdx.x; d < DIM; d += blockDim.x) {
        float x = row[d];
        ss += x * x;
    }
    __shared__ float sm[8];
    for (int o = 16; o; o >>= 1) ss += __shfl_xor_sync(0xffffffffu, ss, o);
    if ((threadIdx.x & 31) == 0) sm[threadIdx.x >> 5] = ss;
    __syncthreads();
    if (threadIdx.x == 0) {
        float tot = 0.f;
        for (int w = 0; w < 8; w++) tot += sm[w];
        bool isU8 = false;
        for (int j = 1; j < N_TXT; j++) {
            if ((j & 3) != 0 && maskb[j] != 0) { isU8 = true; break; }
        }
        bool mv = isU8 ? (maskb[t] != 0) : (((const int*)maskb)[t] != 0);
        float n = fmaxf(sqrtf(tot), 1e-8f);
        g_invn[t] = mv ? (1.f / n) : 0.f;
    }
}

// ---------------------------------------------------------------------------
// Kernel 1b: v[d] = sum_t emb[t][d] * invn[t]   (coalesced column walk)
// ---------------------------------------------------------------------------
__global__ void k_buildv(const float* __restrict__ emb) {
    int d = blockIdx.x * blockDim.x + threadIdx.x;
    float acc = 0.f;
#pragma unroll 4
    for (int t = 0; t < N_TXT; t++)
        acc = fmaf(emb[(size_t)t * DIM + d], g_invn[t], acc);
    g_v[d] = acc;
}

// ---------------------------------------------------------------------------
// Kernel 2: per image row: dot(f_i, v) and ||f_i|| -> sim_sum[i]
// One block (256 thr) per row, float4 streaming; v stays L2/L1-resident.
// ---------------------------------------------------------------------------
__global__ void k_simdot(const float* __restrict__ lf) {
    int i = blockIdx.x;
    const float4* row = (const float4*)(lf + (size_t)i * DIM);
    const float4* v4  = (const float4*)g_v;
    float dot = 0.f, ss = 0.f;
#pragma unroll
    for (int it = 0; it < 4; it++) {
        int idx = it * 256 + threadIdx.x;
        float4 a = row[idx];
        float4 b = v4[idx];
        dot += a.x * b.x + a.y * b.y + a.z * b.z + a.w * b.w;
        ss  += a.x * a.x + a.y * a.y + a.z * a.z + a.w * a.w;
    }
    __shared__ float sd[8], sq[8];
    for (int o = 16; o; o >>= 1) {
        dot += __shfl_xor_sync(0xffffffffu, dot, o);
        ss  += __shfl_xor_sync(0xffffffffu, ss, o);
    }
    if ((threadIdx.x & 31) == 0) { sd[threadIdx.x >> 5] = dot; sq[threadIdx.x >> 5] = ss; }
    __syncthreads();
    if (threadIdx.x == 0) {
        float d = 0.f, s = 0.f;
        for (int w = 0; w < 8; w++) { d += sd[w]; s += sq[w]; }
        float n = fmaxf(sqrtf(s), 1e-8f);
        g_sim[i] = d / n;
    }
}

// ---------------------------------------------------------------------------
// Kernel 3: single block. softmax(2*sim) + gumbel, softmax again, exact rank
// via monotonic-float-bit bucket histogram, double-precision cumsum of sorted
// probs, top-p count -> keep mask.
// Shared layout (bytes):
//   probs : [0,      18432)
//   P     : [18432,  83968)   NB ints (hist -> exclusive starts -> ends)
//   lst   : [83968,  102400)  element ids grouped by bucket
//   rnk   : [102400, 120832)
//   sortv : [120832, 139264)
//   daux  : [139264, 147456)  1024 doubles
//   iaux  : [147456, 151552)  1024 ints
//   red   : [151552, 151680)  32 floats
// ---------------------------------------------------------------------------
#define SMEM3 151680

__device__ __forceinline__ unsigned mono_bits(float p) {
    unsigned u = __float_as_uint(p);
    return (u >> 31) ? ~u : (u | 0x80000000u);
}

__global__ void k_topp(const float* __restrict__ gnoise) {
    extern __shared__ unsigned char sraw[];
    float*  probs = (float*)(sraw);
    int*    P     = (int*)(sraw + 18432);
    int*    lst   = (int*)(sraw + 83968);
    int*    rnk   = (int*)(sraw + 102400);
    float*  sortv = (float*)(sraw + 120832);
    double* daux  = (double*)(sraw + 139264);
    int*    iaux  = (int*)(sraw + 147456);
    float*  red   = (float*)(sraw + 151552);
    int tid = threadIdx.x;

    // ---- softmax #1 over 2*sim ----
    float lm = -INFINITY;
    for (int i = tid; i < N_IMG; i += NTH) {
        float t = 2.f * g_sim[i];
        probs[i] = t;
        lm = fmaxf(lm, t);
    }
    for (int o = 16; o; o >>= 1) lm = fmaxf(lm, __shfl_xor_sync(0xffffffffu, lm, o));
    if ((tid & 31) == 0) red[tid >> 5] = lm;
    __syncthreads();
    if (tid < 32) {
        float x = red[tid];
        for (int o = 16; o; o >>= 1) x = fmaxf(x, __shfl_xor_sync(0xffffffffu, x, o));
        if (tid == 0) red[0] = x;
    }
    __syncthreads();
    float m1 = red[0];
    __syncthreads();

    float lsum = 0.f;
    for (int i = tid; i < N_IMG; i += NTH) {
        float e = expf(probs[i] - m1);
        probs[i] = e;
        lsum += e;
    }
    for (int o = 16; o; o >>= 1) lsum += __shfl_xor_sync(0xffffffffu, lsum, o);
    if ((tid & 31) == 0) red[tid >> 5] = lsum;
    __syncthreads();
    if (tid < 32) {
        float x = red[tid];
        for (int o = 16; o; o >>= 1) x += __shfl_xor_sync(0xffffffffu, x, o);
        if (tid == 0) red[0] = x;
    }
    __syncthreads();
    float Z1 = red[0];
    __syncthreads();

    // ---- add gumbel, softmax #2 max ----
    float lm2 = -INFINITY;
    for (int i = tid; i < N_IMG; i += NTH) {
        float z = probs[i] / Z1 + gnoise[i];
        probs[i] = z;
        lm2 = fmaxf(lm2, z);
    }
    for (int o = 16; o; o >>= 1) lm2 = fmaxf(lm2, __shfl_xor_sync(0xffffffffu, lm2, o));
    if ((tid & 31) == 0) red[tid >> 5] = lm2;
    __syncthreads();
    if (tid < 32) {
        float x = red[tid];
        for (int o = 16; o; o >>= 1) x = fmaxf(x, __shfl_xor_sync(0xffffffffu, x, o));
        if (tid == 0) red[0] = x;
    }
    __syncthreads();
    float m2 = red[0];
    __syncthreads();

    float ls2 = 0.f;
    for (int i = tid; i < N_IMG; i += NTH) {
        float e = expf(probs[i] - m2);
        probs[i] = e;
        ls2 += e;
    }
    for (int o = 16; o; o >>= 1) ls2 += __shfl_xor_sync(0xffffffffu, ls2, o);
    if ((tid & 31) == 0) red[tid >> 5] = ls2;
    __syncthreads();
    if (tid < 32) {
        float x = red[tid];
        for (int o = 16; o; o >>= 1) x += __shfl_xor_sync(0xffffffffu, x, o);
        if (tid == 0) red[0] = x;
    }
    __syncthreads();
    float Z2 = red[0];

    // ---- zero histogram ----
    for (int b = tid; b < NB; b += NTH) P[b] = 0;
    __syncthreads();

    // ---- normalize + histogram (bucket 0 = largest probs) ----
    for (int i = tid; i < N_IMG; i += NTH) {
        float p = probs[i] / Z2;
        probs[i] = p;
        int bd = (NB - 1) - (int)(mono_bits(p) >> 18);
        atomicAdd(&P[bd], 1);
    }
    __syncthreads();

    // ---- exclusive scan over NB buckets (chunked) ----
    const int CB = NB / NTH;  // 16
    int base = tid * CB;
    int run = 0;
#pragma unroll
    for (int j = 0; j < CB; j++) {
        int t = P[base + j];
        P[base + j] = run;
        run += t;
    }
    int mytot = run;
    iaux[tid] = run;
    __syncthreads();
    for (int off = 1; off < NTH; off <<= 1) {
        int t = (tid >= off) ? iaux[tid - off] : 0;
        __syncthreads();
        iaux[tid] += t;
        __syncthreads();
    }
    int excl = iaux[tid] - mytot;
    if (excl) {
#pragma unroll
        for (int j = 0; j < CB; j++) P[base + j] += excl;
    }
    __syncthreads();

    // ---- scatter element ids by bucket (P becomes bucket ends) ----
    for (int i = tid; i < N_IMG; i += NTH) {
        int bd = (NB - 1) - (int)(mono_bits(probs[i]) >> 18);
        int pos = atomicAdd(&P[bd], 1);
        lst[pos] = i;
    }
    __syncthreads();

    // ---- exact rank: descending prob, ties -> lower index first ----
    for (int i = tid; i < N_IMG; i += NTH) {
        float p = probs[i];
        int bd = (NB - 1) - (int)(mono_bits(p) >> 18);
        int start = bd ? P[bd - 1] : 0;
        int end = P[bd];
        int r = start;
        for (int q = start; q < end; q++) {
            int j = lst[q];
            float pj = probs[j];
            if (pj > p || (pj == p && j < i)) r++;
        }
        rnk[i] = r;
        sortv[r] = p;
    }
    __syncthreads();

    // ---- double-precision cumsum of sorted probs + top-p count ----
    const int CE = (N_IMG + NTH - 1) / NTH;  // 5
    int s0 = tid * CE;
    double loc = 0.0;
    for (int j = 0; j < CE; j++) {
        int idx = s0 + j;
        if (idx < N_IMG) loc += (double)sortv[idx];
    }
    double mt = loc;
    daux[tid] = loc;
    __syncthreads();
    for (int off = 1; off < NTH; off <<= 1) {
        double t = (tid >= off) ? daux[tid - off] : 0.0;
        __syncthreads();
        daux[tid] += t;
        __syncthreads();
    }
    double ex = daux[tid] - mt;
    const double TOPPD = (double)0.9f;  // jax promotes 0.9 -> f32
    int c = 0;
    double runc = ex;
    for (int j = 0; j < CE; j++) {
        int idx = s0 + j;
        if (idx < N_IMG) {
            runc += (double)sortv[idx];
            if (runc <= TOPPD) c++;
        }
    }
    for (int o = 16; o; o >>= 1) c += __shfl_xor_sync(0xffffffffu, c, o);
    if ((tid & 31) == 0) iaux[tid >> 5] = c;
    __syncthreads();
    if (tid == 0) {
        int tot = 0;
        for (int w = 0; w < NTH / 32; w++) tot += iaux[w];
        int k = tot + 1;
        if (k > N_IMG) k = N_IMG;
        iaux[0] = k;
    }
    __syncthreads();
    int k = iaux[0];
    for (int i = tid; i < N_IMG; i += NTH) g_keep[i] = (rnk[i] < k) ? 1 : 0;
}

// ---------------------------------------------------------------------------
// Kernel 4: out[i] = keep[i] ? local_f[i] : 0   (row copy, float4)
// ---------------------------------------------------------------------------
__global__ void k_writeout(const float* __restrict__ lf, float* __restrict__ out) {
    int i = blockIdx.x;
    const float4* src = (const float4*)(lf + (size_t)i * DIM);
    float4* dst = (float4*)(out + (size_t)i * DIM);
    if (g_keep[i]) {
#pragma unroll
        for (int it = 0; it < 4; it++) {
            int idx = it * 256 + threadIdx.x;
            dst[idx] = src[idx];
        }
    } else {
        float4 z = make_float4(0.f, 0.f, 0.f, 0.f);
#pragma unroll
        for (int it = 0; it < 4; it++) {
            int idx = it * 256 + threadIdx.x;
            dst[idx] = z;
        }
    }
}

// ---------------------------------------------------------------------------
extern "C" void kernel_launch(void* const* d_in, const int* in_sizes, int n_in,
                              void* d_out, int out_size) {
    const float*         lf   = (const float*)d_in[0];
    const float*         emb  = (const float*)d_in[1];
    const unsigned char* mask = (const unsigned char*)d_in[2];
    const float*         gn   = (const float*)d_in[3];
    float*               out  = (float*)d_out;

    cudaFuncSetAttribute(k_topp, cudaFuncAttributeMaxDynamicSharedMemorySize, SMEM3);

    k_textnorm<<<N_TXT, 256>>>(emb, mask);
    k_buildv<<<DIM / 256, 256>>>(emb);
    k_simdot<<<N_IMG, 256>>>(lf);
    k_topp<<<1, NTH, SMEM3>>>(gn);
    k_writeout<<<N_IMG, 256>>>(lf, out);
}

// round 4
// speedup vs baseline: 1.9403x; 1.9403x over previous
#include <cuda_runtime.h>
#include <math.h>
#include <stdint.h>

#define N_IMG 4608
#define N_TXT 128
#define DIM   4096
#define NB    16384
#define NTH   1024

// ---- scratch (no allocations allowed) ----
__device__ float g_v[DIM];
__device__ float g_invn[N_TXT];
__device__ float g_sim[N_IMG];
__device__ unsigned char g_keep[N_IMG];

// ---------------------------------------------------------------------------
// Kernel 1a: per-text-row inverse norm, masked. Also probes whether the bool
// mask is stored as 1 byte/elem or int32/elem (little-endian): an int32 bool
// array has zero bytes at offsets j with j%4!=0.
// ---------------------------------------------------------------------------
__global__ void k_textnorm(const float* __restrict__ emb,
                           const unsigned char* __restrict__ maskb) {
    int t = blockIdx.x;
    const float* row = emb + (size_t)t * DIM;
    float ss = 0.f;
    for (int d = threadIdx.x; d < DIM; d += blockDim.x) {
        float x = row[d];
        ss += x * x;
    }
    __shared__ float sm[8];
    for (int o = 16; o; o >>= 1) ss += __shfl_xor_sync(0xffffffffu, ss, o);
    if ((threadIdx.x & 31) == 0) sm[threadIdx.x >> 5] = ss;
    __syncthreads();
    if (threadIdx.x == 0) {
        float tot = 0.f;
        for (int w = 0; w < 8; w++) tot += sm[w];
        bool isU8 = false;
        for (int j = 1; j < N_TXT; j++) {
            if ((j & 3) != 0 && maskb[j] != 0) { isU8 = true; break; }
        }
        bool mv = isU8 ? (maskb[t] != 0) : (((const int*)maskb)[t] != 0);
        float n = fmaxf(sqrtf(tot), 1e-8f);
        g_invn[t] = mv ? (1.f / n) : 0.f;
    }
}

// ---------------------------------------------------------------------------
// Kernel 1b: v[d] = sum_t emb[t][d] * invn[t]   (coalesced column walk)
// ---------------------------------------------------------------------------
__global__ void k_buildv(const float* __restrict__ emb) {
    int d = blockIdx.x * blockDim.x + threadIdx.x;
    float acc = 0.f;
#pragma unroll 4
    for (int t = 0; t < N_TXT; t++)
        acc = fmaf(emb[(size_t)t * DIM + d], g_invn[t], acc);
    g_v[d] = acc;
}

// ---------------------------------------------------------------------------
// Kernel 2: per image row: dot(f_i, v) and ||f_i|| -> sim_sum[i]
// One block (256 thr) per row, float4 streaming; v stays L2/L1-resident.
// ---------------------------------------------------------------------------
__global__ void k_simdot(const float* __restrict__ lf) {
    int i = blockIdx.x;
    const float4* row = (const float4*)(lf + (size_t)i * DIM);
    const float4* v4  = (const float4*)g_v;
    float dot = 0.f, ss = 0.f;
#pragma unroll
    for (int it = 0; it < 4; it++) {
        int idx = it * 256 + threadIdx.x;
        float4 a = row[idx];
        float4 b = v4[idx];
        dot += a.x * b.x + a.y * b.y + a.z * b.z + a.w * b.w;
        ss  += a.x * a.x + a.y * a.y + a.z * a.z + a.w * a.w;
    }
    __shared__ float sd[8], sq[8];
    for (int o = 16; o; o >>= 1) {
        dot += __shfl_xor_sync(0xffffffffu, dot, o);
        ss  += __shfl_xor_sync(0xffffffffu, ss, o);
    }
    if ((threadIdx.x & 31) == 0) { sd[threadIdx.x >> 5] = dot; sq[threadIdx.x >> 5] = ss; }
    __syncthreads();
    if (threadIdx.x == 0) {
        float d = 0.f, s = 0.f;
        for (int w = 0; w < 8; w++) { d += sd[w]; s += sq[w]; }
        float n = fmaxf(sqrtf(s), 1e-8f);
        g_sim[i] = d / n;
    }
}

// ---------------------------------------------------------------------------
// Kernel 3: single block. softmax(2*sim) + gumbel, softmax again, exact rank
// via LINEAR-valued bucket histogram (16384 buckets over [pmin,pmax] -> ~1-10
// elems/bucket for this distribution), double-precision cumsum of sorted
// probs, top-p count -> keep mask.
// Shared layout (bytes):
//   probs : [0,      18432)
//   P     : [18432,  83968)   NB ints (hist -> exclusive starts -> ends)
//   lst   : [83968,  102400)  element ids grouped by bucket
//   rnk   : [102400, 120832)
//   sortv : [120832, 139264)
//   daux  : [139264, 147456)  1024 doubles
//   iaux  : [147456, 151552)  1024 ints
//   red   : [151552, 151808)  64 floats (32 warps min + 32 warps max)
// ---------------------------------------------------------------------------
#define SMEM3 151808

__global__ void k_topp(const float* __restrict__ gnoise) {
    extern __shared__ unsigned char sraw[];
    float*  probs = (float*)(sraw);
    int*    P     = (int*)(sraw + 18432);
    int*    lst   = (int*)(sraw + 83968);
    int*    rnk   = (int*)(sraw + 102400);
    float*  sortv = (float*)(sraw + 120832);
    double* daux  = (double*)(sraw + 139264);
    int*    iaux  = (int*)(sraw + 147456);
    float*  red   = (float*)(sraw + 151552);   // 64 floats
    int tid = threadIdx.x;

    // ---- softmax #1 over 2*sim ----
    float lm = -INFINITY;
    for (int i = tid; i < N_IMG; i += NTH) {
        float t = 2.f * g_sim[i];
        probs[i] = t;
        lm = fmaxf(lm, t);
    }
    for (int o = 16; o; o >>= 1) lm = fmaxf(lm, __shfl_xor_sync(0xffffffffu, lm, o));
    if ((tid & 31) == 0) red[tid >> 5] = lm;
    __syncthreads();
    if (tid < 32) {
        float x = red[tid];
        for (int o = 16; o; o >>= 1) x = fmaxf(x, __shfl_xor_sync(0xffffffffu, x, o));
        if (tid == 0) red[0] = x;
    }
    __syncthreads();
    float m1 = red[0];
    __syncthreads();

    float lsum = 0.f;
    for (int i = tid; i < N_IMG; i += NTH) {
        float e = expf(probs[i] - m1);
        probs[i] = e;
        lsum += e;
    }
    for (int o = 16; o; o >>= 1) lsum += __shfl_xor_sync(0xffffffffu, lsum, o);
    if ((tid & 31) == 0) red[tid >> 5] = lsum;
    __syncthreads();
    if (tid < 32) {
        float x = red[tid];
        for (int o = 16; o; o >>= 1) x += __shfl_xor_sync(0xffffffffu, x, o);
        if (tid == 0) red[0] = x;
    }
    __syncthreads();
    float Z1 = red[0];
    __syncthreads();

    // ---- add gumbel, softmax #2 max ----
    float lm2 = -INFINITY;
    for (int i = tid; i < N_IMG; i += NTH) {
        float z = probs[i] / Z1 + gnoise[i];
        probs[i] = z;
        lm2 = fmaxf(lm2, z);
    }
    for (int o = 16; o; o >>= 1) lm2 = fmaxf(lm2, __shfl_xor_sync(0xffffffffu, lm2, o));
    if ((tid & 31) == 0) red[tid >> 5] = lm2;
    __syncthreads();
    if (tid < 32) {
        float x = red[tid];
        for (int o = 16; o; o >>= 1) x = fmaxf(x, __shfl_xor_sync(0xffffffffu, x, o));
        if (tid == 0) red[0] = x;
    }
    __syncthreads();
    float m2 = red[0];
    __syncthreads();

    float ls2 = 0.f;
    for (int i = tid; i < N_IMG; i += NTH) {
        float e = expf(probs[i] - m2);
        probs[i] = e;
        ls2 += e;
    }
    for (int o = 16; o; o >>= 1) ls2 += __shfl_xor_sync(0xffffffffu, ls2, o);
    if ((tid & 31) == 0) red[tid >> 5] = ls2;
    __syncthreads();
    if (tid < 32) {
        float x = red[tid];
        for (int o = 16; o; o >>= 1) x += __shfl_xor_sync(0xffffffffu, x, o);
        if (tid == 0) red[0] = x;
    }
    __syncthreads();
    float Z2 = red[0];
    __syncthreads();

    // ---- normalize p = e/Z2; track pmin/pmax for linear bucketing ----
    float lmin = INFINITY, lmax = -INFINITY;
    for (int i = tid; i < N_IMG; i += NTH) {
        float p = probs[i] / Z2;
        probs[i] = p;
        lmin = fminf(lmin, p);
        lmax = fmaxf(lmax, p);
    }
    for (int o = 16; o; o >>= 1) {
        lmin = fminf(lmin, __shfl_xor_sync(0xffffffffu, lmin, o));
        lmax = fmaxf(lmax, __shfl_xor_sync(0xffffffffu, lmax, o));
    }
    if ((tid & 31) == 0) { red[tid >> 5] = lmin; red[32 + (tid >> 5)] = lmax; }
    __syncthreads();
    if (tid < 32) {
        float a = red[tid];
        float b = red[32 + tid];
        for (int o = 16; o; o >>= 1) {
            a = fminf(a, __shfl_xor_sync(0xffffffffu, a, o));
            b = fmaxf(b, __shfl_xor_sync(0xffffffffu, b, o));
        }
        if (tid == 0) { red[0] = a; red[1] = b; }
    }
    __syncthreads();
    float pmin = red[0];
    float pmax = red[1];
    float scale = (float)(NB - 1) / fmaxf(pmax - pmin, 1e-30f);
    __syncthreads();

    // ---- zero histogram ----
    for (int b = tid; b < NB; b += NTH) P[b] = 0;
    __syncthreads();

    // bucket: descending in p, equal p -> same bucket
#define BUCKET(p) min(max((int)((pmax - (p)) * scale), 0), NB - 1)

    // ---- histogram ----
    for (int i = tid; i < N_IMG; i += NTH) {
        int bd = BUCKET(probs[i]);
        atomicAdd(&P[bd], 1);
    }
    __syncthreads();

    // ---- exclusive scan over NB buckets (chunked) ----
    const int CB = NB / NTH;  // 16
    int base = tid * CB;
    int run = 0;
#pragma unroll
    for (int j = 0; j < CB; j++) {
        int t = P[base + j];
        P[base + j] = run;
        run += t;
    }
    int mytot = run;
    iaux[tid] = run;
    __syncthreads();
    for (int off = 1; off < NTH; off <<= 1) {
        int t = (tid >= off) ? iaux[tid - off] : 0;
        __syncthreads();
        iaux[tid] += t;
        __syncthreads();
    }
    int excl = iaux[tid] - mytot;
    if (excl) {
#pragma unroll
        for (int j = 0; j < CB; j++) P[base + j] += excl;
    }
    __syncthreads();

    // ---- scatter element ids by bucket (P becomes bucket ends) ----
    for (int i = tid; i < N_IMG; i += NTH) {
        int bd = BUCKET(probs[i]);
        int pos = atomicAdd(&P[bd], 1);
        lst[pos] = i;
    }
    __syncthreads();

    // ---- exact rank: descending prob, ties -> lower index first ----
    for (int i = tid; i < N_IMG; i += NTH) {
        float p = probs[i];
        int bd = BUCKET(p);
        int start = bd ? P[bd - 1] : 0;
        int end = P[bd];
        int r = start;
        for (int q = start; q < end; q++) {
            int j = lst[q];
            float pj = probs[j];
            if (pj > p || (pj == p && j < i)) r++;
        }
        rnk[i] = r;
        sortv[r] = p;
    }
    __syncthreads();

    // ---- double-precision cumsum of sorted probs + top-p count ----
    const int CE = (N_IMG + NTH - 1) / NTH;  // 5
    int s0 = tid * CE;
    double loc = 0.0;
    for (int j = 0; j < CE; j++) {
        int idx = s0 + j;
        if (idx < N_IMG) loc += (double)sortv[idx];
    }
    double mt = loc;
    daux[tid] = loc;
    __syncthreads();
    for (int off = 1; off < NTH; off <<= 1) {
        double t = (tid >= off) ? daux[tid - off] : 0.0;
        __syncthreads();
        daux[tid] += t;
        __syncthreads();
    }
    double ex = daux[tid] - mt;
    const double TOPPD = (double)0.9f;  // jax promotes 0.9 -> f32
    int c = 0;
    double runc = ex;
    for (int j = 0; j < CE; j++) {
        int idx = s0 + j;
        if (idx < N_IMG) {
            runc += (double)sortv[idx];
            if (runc <= TOPPD) c++;
        }
    }
    for (int o = 16; o; o >>= 1) c += __shfl_xor_sync(0xffffffffu, c, o);
    if ((tid & 31) == 0) iaux[tid >> 5] = c;
    __syncthreads();
    if (tid == 0) {
        int tot = 0;
        for (int w = 0; w < NTH / 32; w++) tot += iaux[w];
        int k = tot + 1;
        if (k > N_IMG) k = N_IMG;
        iaux[0] = k;
    }
    __syncthreads();
    int k = iaux[0];
    for (int i = tid; i < N_IMG; i += NTH) g_keep[i] = (rnk[i] < k) ? 1 : 0;
#undef BUCKET
}

// ---------------------------------------------------------------------------
// Kernel 4: out[i] = keep[i] ? local_f[i] : 0   (row copy, float4)
// ---------------------------------------------------------------------------
__global__ void k_writeout(const float* __restrict__ lf, float* __restrict__ out) {
    int i = blockIdx.x;
    const float4* src = (const float4*)(lf + (size_t)i * DIM);
    float4* dst = (float4*)(out + (size_t)i * DIM);
    if (g_keep[i]) {
#pragma unroll
        for (int it = 0; it < 4; it++) {
            int idx = it * 256 + threadIdx.x;
            dst[idx] = src[idx];
        }
    } else {
        float4 z = make_float4(0.f, 0.f, 0.f, 0.f);
#pragma unroll
        for (int it = 0; it < 4; it++) {
            int idx = it * 256 + threadIdx.x;
            dst[idx] = z;
        }
    }
}

// ---------------------------------------------------------------------------
extern "C" void kernel_launch(void* const* d_in, const int* in_sizes, int n_in,
                              void* d_out, int out_size) {
    const float*         lf   = (const float*)d_in[0];
    const float*         emb  = (const float*)d_in[1];
    const unsigned char* mask = (const unsigned char*)d_in[2];
    const float*         gn   = (const float*)d_in[3];
    float*               out  = (float*)d_out;

    cudaFuncSetAttribute(k_topp, cudaFuncAttributeMaxDynamicSharedMemorySize, SMEM3);

    k_textnorm<<<N_TXT, 256>>>(emb, mask);
    k_buildv<<<DIM / 256, 256>>>(emb);
    k_simdot<<<N_IMG, 256>>>(lf);
    k_topp<<<1, NTH, SMEM3>>>(gn);
    k_writeout<<<N_IMG, 256>>>(lf, out);
}

// round 5
// speedup vs baseline: 2.0446x; 1.0537x over previous
#include <cuda_runtime.h>
#include <math.h>
#include <stdint.h>

#define N_IMG 4608
#define N_TXT 128
#define DIM   4096
#define NB    16384
#define NTH   1024
#define CE    5          // elements per thread in k_topp (ceil(4608/1024))

// ---- scratch (no allocations allowed) ----
__device__ float g_v[DIM];
__device__ float g_invn[N_TXT];
__device__ float g_sim[N_IMG];
__device__ unsigned char g_keep[N_IMG];

// ---------------------------------------------------------------------------
// Kernel 1a: per-text-row inverse norm, masked (with bool-layout probe).
// ---------------------------------------------------------------------------
__global__ void k_textnorm(const float* __restrict__ emb,
                           const unsigned char* __restrict__ maskb) {
    int t = blockIdx.x;
    const float* row = emb + (size_t)t * DIM;
    float ss = 0.f;
    for (int d = threadIdx.x; d < DIM; d += blockDim.x) {
        float x = row[d];
        ss += x * x;
    }
    __shared__ float sm[8];
    for (int o = 16; o; o >>= 1) ss += __shfl_xor_sync(0xffffffffu, ss, o);
    if ((threadIdx.x & 31) == 0) sm[threadIdx.x >> 5] = ss;
    __syncthreads();
    if (threadIdx.x == 0) {
        float tot = 0.f;
        for (int w = 0; w < 8; w++) tot += sm[w];
        bool isU8 = false;
        for (int j = 1; j < N_TXT; j++) {
            if ((j & 3) != 0 && maskb[j] != 0) { isU8 = true; break; }
        }
        bool mv = isU8 ? (maskb[t] != 0) : (((const int*)maskb)[t] != 0);
        float n = fmaxf(sqrtf(tot), 1e-8f);
        g_invn[t] = mv ? (1.f / n) : 0.f;
    }
}

// ---------------------------------------------------------------------------
// Kernel 1b: v[d] = sum_t emb[t][d] * invn[t]
// ---------------------------------------------------------------------------
__global__ void k_buildv(const float* __restrict__ emb) {
    int d = blockIdx.x * blockDim.x + threadIdx.x;
    float acc = 0.f;
#pragma unroll 4
    for (int t = 0; t < N_TXT; t++)
        acc = fmaf(emb[(size_t)t * DIM + d], g_invn[t], acc);
    g_v[d] = acc;
}

// ---------------------------------------------------------------------------
// Kernel 2: per image row: dot(f_i, v) and ||f_i|| -> sim_sum[i]
// ---------------------------------------------------------------------------
__global__ void k_simdot(const float* __restrict__ lf) {
    int i = blockIdx.x;
    const float4* row = (const float4*)(lf + (size_t)i * DIM);
    const float4* v4  = (const float4*)g_v;
    float dot = 0.f, ss = 0.f;
#pragma unroll
    for (int it = 0; it < 4; it++) {
        int idx = it * 256 + threadIdx.x;
        float4 a = row[idx];
        float4 b = v4[idx];
        dot += a.x * b.x + a.y * b.y + a.z * b.z + a.w * b.w;
        ss  += a.x * a.x + a.y * a.y + a.z * a.z + a.w * a.w;
    }
    __shared__ float sd[8], sq[8];
    for (int o = 16; o; o >>= 1) {
        dot += __shfl_xor_sync(0xffffffffu, dot, o);
        ss  += __shfl_xor_sync(0xffffffffu, ss, o);
    }
    if ((threadIdx.x & 31) == 0) { sd[threadIdx.x >> 5] = dot; sq[threadIdx.x >> 5] = ss; }
    __syncthreads();
    if (threadIdx.x == 0) {
        float d = 0.f, s = 0.f;
        for (int w = 0; w < 8; w++) { d += sd[w]; s += sq[w]; }
        float n = fmaxf(sqrtf(s), 1e-8f);
        g_sim[i] = d / n;
    }
}

// ---------------------------------------------------------------------------
// Kernel 3: single block, register-resident pipeline.
// Shared layout (bytes):
//   probs : [0,      18432)   final p values (for cross-thread rank lookups)
//   P     : [18432,  83968)   NB ints (hist -> starts -> ends)
//   lst   : [83968,  102400)  element ids grouped by bucket
//   sortv : [102400, 120832)  probs in descending-rank order
//   daux  : [120832, 121088)  32 doubles (warp totals)
//   iaux  : [121088, 121216)  32 ints
//   red   : [121216, 121472)  64 floats
// ---------------------------------------------------------------------------
#define SMEM3 121472

__device__ __forceinline__ float blk_max(float v, float* red, int tid) {
    for (int o = 16; o; o >>= 1) v = fmaxf(v, __shfl_xor_sync(0xffffffffu, v, o));
    if ((tid & 31) == 0) red[tid >> 5] = v;
    __syncthreads();
    if (tid < 32) {
        float x = red[tid];
        for (int o = 16; o; o >>= 1) x = fmaxf(x, __shfl_xor_sync(0xffffffffu, x, o));
        if (tid == 0) red[0] = x;
    }
    __syncthreads();
    float r = red[0];
    __syncthreads();
    return r;
}

__device__ __forceinline__ float blk_sum(float v, float* red, int tid) {
    for (int o = 16; o; o >>= 1) v += __shfl_xor_sync(0xffffffffu, v, o);
    if ((tid & 31) == 0) red[tid >> 5] = v;
    __syncthreads();
    if (tid < 32) {
        float x = red[tid];
        for (int o = 16; o; o >>= 1) x += __shfl_xor_sync(0xffffffffu, x, o);
        if (tid == 0) red[0] = x;
    }
    __syncthreads();
    float r = red[0];
    __syncthreads();
    return r;
}

__global__ void __launch_bounds__(NTH, 1) k_topp(const float* __restrict__ gnoise) {
    extern __shared__ unsigned char sraw[];
    float*  probs = (float*)(sraw);
    int*    P     = (int*)(sraw + 18432);
    int*    lst   = (int*)(sraw + 83968);
    float*  sortv = (float*)(sraw + 102400);
    double* daux  = (double*)(sraw + 120832);
    int*    iaux  = (int*)(sraw + 121088);
    float*  red   = (float*)(sraw + 121216);
    int tid  = threadIdx.x;
    int lane = tid & 31;
    int w    = tid >> 5;
    int s0   = tid * CE;   // contiguous element chunk [s0, s0+CE)
    int nmine = min(CE, max(0, N_IMG - s0));

    float val[CE];   // register-resident working values
    float pv[CE];    // final probabilities
    int   rk[CE];    // final ranks

    // ---- pass 1: t = 2*sim, max -> m1 ----
    float lm = -INFINITY;
#pragma unroll
    for (int j = 0; j < CE; j++) {
        if (j < nmine) {
            float t = 2.f * g_sim[s0 + j];
            val[j] = t;
            lm = fmaxf(lm, t);
        }
    }
    float m1 = blk_max(lm, red, tid);

    // ---- pass 2: e = exp(t - m1), sum -> Z1 ----
    float lsum = 0.f;
#pragma unroll
    for (int j = 0; j < CE; j++) {
        if (j < nmine) {
            float e = expf(val[j] - m1);
            val[j] = e;
            lsum += e;
        }
    }
    float Z1 = blk_sum(lsum, red, tid);
    float r1 = 1.f / Z1;

    // ---- pass 3: z = e/Z1 + g, max -> m2 ----
    float lm2 = -INFINITY;
#pragma unroll
    for (int j = 0; j < CE; j++) {
        if (j < nmine) {
            float z = val[j] * r1 + gnoise[s0 + j];
            val[j] = z;
            lm2 = fmaxf(lm2, z);
        }
    }
    float m2 = blk_max(lm2, red, tid);

    // ---- pass 4: e2 = exp(z - m2), sum -> Z2, track e2 min/max ----
    float ls2 = 0.f, emin = INFINITY, emax = -INFINITY;
#pragma unroll
    for (int j = 0; j < CE; j++) {
        if (j < nmine) {
            float e = expf(val[j] - m2);
            val[j] = e;
            ls2 += e;
            emin = fminf(emin, e);
            emax = fmaxf(emax, e);
        }
    }
    // combined: sum, min, max in one barrier sequence
    for (int o = 16; o; o >>= 1) {
        ls2  += __shfl_xor_sync(0xffffffffu, ls2, o);
        emin  = fminf(emin, __shfl_xor_sync(0xffffffffu, emin, o));
        emax  = fmaxf(emax, __shfl_xor_sync(0xffffffffu, emax, o));
    }
    if (lane == 0) { red[w] = ls2; red[32 + w] = emin; daux[w] = (double)emax; }
    __syncthreads();
    if (tid < 32) {
        float a = red[tid];
        float b = red[32 + tid];
        float c = (float)daux[tid];
        for (int o = 16; o; o >>= 1) {
            a += __shfl_xor_sync(0xffffffffu, a, o);
            b  = fminf(b, __shfl_xor_sync(0xffffffffu, b, o));
            c  = fmaxf(c, __shfl_xor_sync(0xffffffffu, c, o));
        }
        if (tid == 0) { red[0] = a; red[1] = b; red[2] = c; }
    }
    __syncthreads();
    float Z2 = red[0];
    float pmin = red[1] / Z2;   // p = f32(e2/Z2) is monotone in e2 -> exact min/max
    float pmax = red[2] / Z2;
    float scale = (float)(NB - 1) / fmaxf(pmax - pmin, 1e-30f);
    __syncthreads();

    // ---- zero histogram ----
    for (int b = tid; b < NB; b += NTH) P[b] = 0;

    // ---- p = e2/Z2 (exact div, matches reference rounding), store + hist ----
#define BUCKET(p) min(max((int)((pmax - (p)) * scale), 0), NB - 1)
    __syncthreads();
#pragma unroll
    for (int j = 0; j < CE; j++) {
        if (j < nmine) {
            float p = val[j] / Z2;
            pv[j] = p;
            probs[s0 + j] = p;
            atomicAdd(&P[BUCKET(p)], 1);
        }
    }
    __syncthreads();

    // ---- exclusive scan over NB buckets: serial-per-thread + warp-hier ----
    const int CB = NB / NTH;  // 16
    int base = tid * CB;
    int run = 0;
#pragma unroll
    for (int j = 0; j < CB; j++) {
        int t = P[base + j];
        P[base + j] = run;
        run += t;
    }
    int mytot = run;
    int iv = mytot;
    for (int o = 1; o < 32; o <<= 1) {
        int t = __shfl_up_sync(0xffffffffu, iv, o);
        if (lane >= o) iv += t;
    }
    if (lane == 31) iaux[w] = iv;
    __syncthreads();
    if (tid < 32) {
        int x = iaux[tid];
        for (int o = 1; o < 32; o <<= 1) {
            int t = __shfl_up_sync(0xffffffffu, x, o);
            if (tid >= o) x += t;
        }
        iaux[tid] = x;
    }
    __syncthreads();
    int excl = (iv - mytot) + (w ? iaux[w - 1] : 0);
    if (excl) {
#pragma unroll
        for (int j = 0; j < CB; j++) P[base + j] += excl;
    }
    __syncthreads();

    // ---- scatter ids by bucket (P becomes bucket ends) ----
#pragma unroll
    for (int j = 0; j < CE; j++) {
        if (j < nmine) {
            int bd = BUCKET(pv[j]);
            int pos = atomicAdd(&P[bd], 1);
            lst[pos] = s0 + j;
        }
    }
    __syncthreads();

    // ---- exact rank: descending p, ties -> lower index first ----
#pragma unroll
    for (int j = 0; j < CE; j++) {
        if (j < nmine) {
            float p = pv[j];
            int i = s0 + j;
            int bd = BUCKET(p);
            int start = bd ? P[bd - 1] : 0;
            int end = P[bd];
            int r = start;
            for (int q = start; q < end; q++) {
                int jj = lst[q];
                float pj = probs[jj];
                if (pj > p || (pj == p && jj < i)) r++;
            }
            rk[j] = r;
            sortv[r] = p;
        }
    }
    __syncthreads();

    // ---- double cumsum of sorted probs (warp-hier scan) + top-p count ----
    double loc = 0.0;
#pragma unroll
    for (int j = 0; j < CE; j++) {
        int idx = s0 + j;
        if (idx < N_IMG) loc += (double)sortv[idx];
    }
    double dv = loc;
    for (int o = 1; o < 32; o <<= 1) {
        double t = __shfl_up_sync(0xffffffffu, dv, o);
        if (lane >= o) dv += t;
    }
    if (lane == 31) daux[w] = dv;
    __syncthreads();
    if (tid < 32) {
        double x = daux[tid];
        for (int o = 1; o < 32; o <<= 1) {
            double t = __shfl_up_sync(0xffffffffu, x, o);
            if (tid >= o) x += t;
        }
        daux[tid] = x;
    }
    __syncthreads();
    double ex = (dv - loc) + (w ? daux[w - 1] : 0.0);

    const double TOPPD = (double)0.9f;  // jax promotes 0.9 -> f32
    int c = 0;
    double runc = ex;
#pragma unroll
    for (int j = 0; j < CE; j++) {
        int idx = s0 + j;
        if (idx < N_IMG) {
            runc += (double)sortv[idx];
            if (runc <= TOPPD) c++;
        }
    }
    for (int o = 16; o; o >>= 1) c += __shfl_xor_sync(0xffffffffu, c, o);
    if (lane == 0) iaux[w] = c;
    __syncthreads();
    if (tid < 32) {
        int x = iaux[tid];
        for (int o = 16; o; o >>= 1) x += __shfl_xor_sync(0xffffffffu, x, o);
        if (tid == 0) {
            int k = x + 1;
            if (k > N_IMG) k = N_IMG;
            iaux[0] = k;
        }
    }
    __syncthreads();
    int k = iaux[0];
#pragma unroll
    for (int j = 0; j < CE; j++) {
        if (j < nmine) g_keep[s0 + j] = (rk[j] < k) ? 1 : 0;
    }
#undef BUCKET
}

// ---------------------------------------------------------------------------
// Kernel 4: out[i] = keep[i] ? local_f[i] : 0   (row copy, float4)
// ---------------------------------------------------------------------------
__global__ void k_writeout(const float* __restrict__ lf, float* __restrict__ out) {
    int i = blockIdx.x;
    const float4* src = (const float4*)(lf + (size_t)i * DIM);
    float4* dst = (float4*)(out + (size_t)i * DIM);
    if (g_keep[i]) {
#pragma unroll
        for (int it = 0; it < 4; it++) {
            int idx = it * 256 + threadIdx.x;
            dst[idx] = src[idx];
        }
    } else {
        float4 z = make_float4(0.f, 0.f, 0.f, 0.f);
#pragma unroll
        for (int it = 0; it < 4; it++) {
            int idx = it * 256 + threadIdx.x;
            dst[idx] = z;
        }
    }
}

// ---------------------------------------------------------------------------
extern "C" void kernel_launch(void* const* d_in, const int* in_sizes, int n_in,
                              void* d_out, int out_size) {
    const float*         lf   = (const float*)d_in[0];
    const float*         emb  = (const float*)d_in[1];
    const unsigned char* mask = (const unsigned char*)d_in[2];
    const float*         gn   = (const float*)d_in[3];
    float*               out  = (float*)d_out;

    cudaFuncSetAttribute(k_topp, cudaFuncAttributeMaxDynamicSharedMemorySize, SMEM3);

    k_textnorm<<<N_TXT, 256>>>(emb, mask);
    k_buildv<<<DIM / 256, 256>>>(emb);
    k_simdot<<<N_IMG, 256>>>(lf);
    k_topp<<<1, NTH, SMEM3>>>(gn);
    k_writeout<<<N_IMG, 256>>>(lf, out);
}

// round 6
// speedup vs baseline: 2.1535x; 1.0532x over previous
#include <cuda_runtime.h>
#include <math.h>
#include <stdint.h>

#define N_IMG 4608
#define N_TXT 128
#define DIM   4096
#define NB    4096
#define NTH   1024
#define CE    5          // elements per thread in k_topp (ceil(4608/1024))

// ---- scratch (no allocations allowed) ----
__device__ float g_v[DIM];
__device__ float g_invn[N_TXT];
__device__ float g_sim[N_IMG];
__device__ unsigned char g_keep[N_IMG];

// ---------------------------------------------------------------------------
// Kernel 1a: per-text-row inverse norm, masked (with bool-layout probe).
// ---------------------------------------------------------------------------
__global__ void k_textnorm(const float* __restrict__ emb,
                           const unsigned char* __restrict__ maskb) {
    int t = blockIdx.x;
    const float* row = emb + (size_t)t * DIM;
    float ss = 0.f;
    for (int d = threadIdx.x; d < DIM; d += blockDim.x) {
        float x = row[d];
        ss += x * x;
    }
    __shared__ float sm[8];
    for (int o = 16; o; o >>= 1) ss += __shfl_xor_sync(0xffffffffu, ss, o);
    if ((threadIdx.x & 31) == 0) sm[threadIdx.x >> 5] = ss;
    __syncthreads();
    if (threadIdx.x == 0) {
        float tot = 0.f;
        for (int w = 0; w < 8; w++) tot += sm[w];
        bool isU8 = false;
        for (int j = 1; j < N_TXT; j++) {
            if ((j & 3) != 0 && maskb[j] != 0) { isU8 = true; break; }
        }
        bool mv = isU8 ? (maskb[t] != 0) : (((const int*)maskb)[t] != 0);
        float n = fmaxf(sqrtf(tot), 1e-8f);
        g_invn[t] = mv ? (1.f / n) : 0.f;
    }
}

// ---------------------------------------------------------------------------
// Kernel 1b: v[d] = sum_t emb[t][d] * invn[t]
// ---------------------------------------------------------------------------
__global__ void k_buildv(const float* __restrict__ emb) {
    int d = blockIdx.x * blockDim.x + threadIdx.x;
    float acc = 0.f;
#pragma unroll 4
    for (int t = 0; t < N_TXT; t++)
        acc = fmaf(emb[(size_t)t * DIM + d], g_invn[t], acc);
    g_v[d] = acc;
}

// ---------------------------------------------------------------------------
// Kernel 2: per image row: dot(f_i, v) and ||f_i|| -> sim_sum[i]
// ---------------------------------------------------------------------------
__global__ void k_simdot(const float* __restrict__ lf) {
    int i = blockIdx.x;
    const float4* row = (const float4*)(lf + (size_t)i * DIM);
    const float4* v4  = (const float4*)g_v;
    float dot = 0.f, ss = 0.f;
#pragma unroll
    for (int it = 0; it < 4; it++) {
        int idx = it * 256 + threadIdx.x;
        float4 a = row[idx];
        float4 b = v4[idx];
        dot += a.x * b.x + a.y * b.y + a.z * b.z + a.w * b.w;
        ss  += a.x * a.x + a.y * a.y + a.z * a.z + a.w * a.w;
    }
    __shared__ float sd[8], sq[8];
    for (int o = 16; o; o >>= 1) {
        dot += __shfl_xor_sync(0xffffffffu, dot, o);
        ss  += __shfl_xor_sync(0xffffffffu, ss, o);
    }
    if ((threadIdx.x & 31) == 0) { sd[threadIdx.x >> 5] = dot; sq[threadIdx.x >> 5] = ss; }
    __syncthreads();
    if (threadIdx.x == 0) {
        float d = 0.f, s = 0.f;
        for (int w = 0; w < 8; w++) { d += sd[w]; s += sq[w]; }
        float n = fmaxf(sqrtf(s), 1e-8f);
        g_sim[i] = d / n;
    }
}

// ---------------------------------------------------------------------------
// Kernel 3: single block. Softmax chain in registers, then bucket histogram
// with per-bucket DOUBLE sums. Only the cumsum-crossing bucket and the k-cut
// bucket are resolved element-exactly; all other buckets decided wholesale.
// Shared layout (bytes):
//   pval : [0,     18432)  p values in scatter order (bucket-grouped)
//   lst  : [18432, 36864)  element ids in scatter order
//   P    : [36864, 53248)  NB ints: hist -> starts -> ends
//   S    : [53248, 86016)  NB doubles: bucket sums -> inclusive prefix
//   daux : [86016, 86272)  32 doubles
//   iaux : [86272, 86400)  32 ints
//   red  : [86400, 86656)  64 floats
//   ictl : [86656, 86664)  2 ints (bstar, k)
// ---------------------------------------------------------------------------
#define SMEM3 86720

__device__ __forceinline__ float blk_max(float v, float* red, int tid) {
    for (int o = 16; o; o >>= 1) v = fmaxf(v, __shfl_xor_sync(0xffffffffu, v, o));
    if ((tid & 31) == 0) red[tid >> 5] = v;
    __syncthreads();
    if (tid < 32) {
        float x = red[tid];
        for (int o = 16; o; o >>= 1) x = fmaxf(x, __shfl_xor_sync(0xffffffffu, x, o));
        if (tid == 0) red[0] = x;
    }
    __syncthreads();
    float r = red[0];
    __syncthreads();
    return r;
}

__device__ __forceinline__ float blk_sum(float v, float* red, int tid) {
    for (int o = 16; o; o >>= 1) v += __shfl_xor_sync(0xffffffffu, v, o);
    if ((tid & 31) == 0) red[tid >> 5] = v;
    __syncthreads();
    if (tid < 32) {
        float x = red[tid];
        for (int o = 16; o; o >>= 1) x += __shfl_xor_sync(0xffffffffu, x, o);
        if (tid == 0) red[0] = x;
    }
    __syncthreads();
    float r = red[0];
    __syncthreads();
    return r;
}

__global__ void __launch_bounds__(NTH, 1) k_topp(const float* __restrict__ gnoise) {
    extern __shared__ unsigned char sraw[];
    float*  pval = (float*)(sraw);
    int*    lst  = (int*)(sraw + 18432);
    int*    P    = (int*)(sraw + 36864);
    double* S    = (double*)(sraw + 53248);
    double* daux = (double*)(sraw + 86016);
    int*    iaux = (int*)(sraw + 86272);
    float*  red  = (float*)(sraw + 86400);
    int*    ictl = (int*)(sraw + 86656);
    int tid  = threadIdx.x;
    int lane = tid & 31;
    int w    = tid >> 5;
    int s0   = tid * CE;
    int nmine = min(CE, max(0, N_IMG - s0));

    float val[CE];
    float pv[CE];

    // ---- pass 1: t = 2*sim, max -> m1 ----
    float lm = -INFINITY;
#pragma unroll
    for (int j = 0; j < CE; j++) {
        if (j < nmine) {
            float t = 2.f * g_sim[s0 + j];
            val[j] = t;
            lm = fmaxf(lm, t);
        }
    }
    float m1 = blk_max(lm, red, tid);

    // ---- pass 2: e = exp(t - m1), sum -> Z1 ----
    float lsum = 0.f;
#pragma unroll
    for (int j = 0; j < CE; j++) {
        if (j < nmine) {
            float e = expf(val[j] - m1);
            val[j] = e;
            lsum += e;
        }
    }
    float Z1 = blk_sum(lsum, red, tid);
    float r1 = 1.f / Z1;

    // ---- pass 3: z = e/Z1 + g, max -> m2 ----
    float lm2 = -INFINITY;
#pragma unroll
    for (int j = 0; j < CE; j++) {
        if (j < nmine) {
            float z = val[j] * r1 + gnoise[s0 + j];
            val[j] = z;
            lm2 = fmaxf(lm2, z);
        }
    }
    float m2 = blk_max(lm2, red, tid);

    // ---- pass 4: e2 = exp(z - m2); sum + min/max in one reduction ----
    float ls2 = 0.f, emin = INFINITY, emax = -INFINITY;
#pragma unroll
    for (int j = 0; j < CE; j++) {
        if (j < nmine) {
            float e = expf(val[j] - m2);
            val[j] = e;
            ls2 += e;
            emin = fminf(emin, e);
            emax = fmaxf(emax, e);
        }
    }
    for (int o = 16; o; o >>= 1) {
        ls2  += __shfl_xor_sync(0xffffffffu, ls2, o);
        emin  = fminf(emin, __shfl_xor_sync(0xffffffffu, emin, o));
        emax  = fmaxf(emax, __shfl_xor_sync(0xffffffffu, emax, o));
    }
    if (lane == 0) { red[w] = ls2; red[32 + w] = emin; daux[w] = (double)emax; }
    __syncthreads();
    if (tid < 32) {
        float a = red[tid];
        float b = red[32 + tid];
        float c = (float)daux[tid];
        for (int o = 16; o; o >>= 1) {
            a += __shfl_xor_sync(0xffffffffu, a, o);
            b  = fminf(b, __shfl_xor_sync(0xffffffffu, b, o));
            c  = fmaxf(c, __shfl_xor_sync(0xffffffffu, c, o));
        }
        if (tid == 0) { red[0] = a; red[1] = b; red[2] = c; }
    }
    __syncthreads();
    float Z2 = red[0];
    float pmin = red[1] / Z2;   // p=f32(e2/Z2) monotone in e2 -> exact min/max
    float pmax = red[2] / Z2;
    float scale = (float)(NB - 1) / fmaxf(pmax - pmin, 1e-30f);
    __syncthreads();

    // ---- zero histogram + sums; init ctl ----
    for (int b = tid; b < NB; b += NTH) { P[b] = 0; S[b] = 0.0; }
    if (tid == 0) ictl[0] = NB;
    __syncthreads();

#define BUCKET(p) min(max((int)((pmax - (p)) * scale), 0), NB - 1)

    // ---- p = e2/Z2 (exact div, reference rounding); count + double sum ----
#pragma unroll
    for (int j = 0; j < CE; j++) {
        if (j < nmine) {
            float p = val[j] / Z2;
            pv[j] = p;
            int bd = BUCKET(p);
            atomicAdd(&P[bd], 1);
            atomicAdd(&S[bd], (double)p);
        }
    }
    __syncthreads();

    // ---- fused scans: P -> exclusive starts, S -> inclusive double prefix ----
    const int CB = NB / NTH;  // 4
    int base = tid * CB;
    int run = 0; double drun = 0.0;
#pragma unroll
    for (int j = 0; j < CB; j++) {
        int t = P[base + j];
        P[base + j] = run;
        run += t;
        drun += S[base + j];
        S[base + j] = drun;          // inclusive within chunk
    }
    int iv = run; double dv = drun;
    for (int o = 1; o < 32; o <<= 1) {
        int ti = __shfl_up_sync(0xffffffffu, iv, o);
        double td = __shfl_up_sync(0xffffffffu, dv, o);
        if (lane >= o) { iv += ti; dv += td; }
    }
    if (lane == 31) { iaux[w] = iv; daux[w] = dv; }
    __syncthreads();
    if (tid < 32) {
        int x = iaux[tid]; double y = daux[tid];
        for (int o = 1; o < 32; o <<= 1) {
            int ti = __shfl_up_sync(0xffffffffu, x, o);
            double td = __shfl_up_sync(0xffffffffu, y, o);
            if (tid >= o) { x += ti; y += td; }
        }
        iaux[tid] = x; daux[tid] = y;
    }
    __syncthreads();
    int iexcl = (iv - run) + (w ? iaux[w - 1] : 0);
    double dexcl = (dv - drun) + (w ? daux[w - 1] : 0.0);
    if (iexcl) {
#pragma unroll
        for (int j = 0; j < CB; j++) P[base + j] += iexcl;
    }
    if (dexcl != 0.0) {
#pragma unroll
        for (int j = 0; j < CB; j++) S[base + j] += dexcl;
    }
    __syncthreads();

    // ---- scatter (p, id) by bucket; P becomes bucket ends ----
#pragma unroll
    for (int j = 0; j < CE; j++) {
        if (j < nmine) {
            int bd = BUCKET(pv[j]);
            int pos = atomicAdd(&P[bd], 1);
            lst[pos] = s0 + j;
            pval[pos] = pv[j];
        }
    }
    __syncthreads();

    const double TOPPD = (double)0.9f;  // jax promotes 0.9 -> f32

    // ---- find crossing bucket b*: S[b*] > 0.9 >= S[b*-1] ----
#pragma unroll
    for (int j = 0; j < CB; j++) {
        int b = base + j;
        double incl = S[b];
        double prev = b ? S[b - 1] : 0.0;
        if (incl > TOPPD && prev <= TOPPD) atomicMin(&ictl[0], b);
    }
    __syncthreads();
    int bstar = ictl[0];

    // ---- warp 0: resolve crossing bucket element-exactly -> count, k ----
    if (w == 0) {
        int count;
        if (bstar >= NB) {
            count = N_IMG;   // total <= 0.9 (cannot happen for softmax, but safe)
        } else {
            int start = bstar ? P[bstar - 1] : 0;
            int end = P[bstar];
            double pref = bstar ? S[bstar - 1] : 0.0;
            int cin = 0;
            for (int q = start + lane; q < end; q += 32) {
                float p = pval[q];
                int id = lst[q];
                double sb = 0.0;
                for (int r = start; r < end; r++) {
                    float pr = pval[r];
                    int ir = lst[r];
                    if (pr > p || (pr == p && ir <= id)) sb += (double)pr;
                }
                if (pref + sb <= TOPPD) cin++;
            }
            for (int o = 16; o; o >>= 1) cin += __shfl_xor_sync(0xffffffffu, cin, o);
            count = start + cin;
        }
        if (lane == 0) {
            int k = count + 1;
            if (k > N_IMG) k = N_IMG;
            ictl[1] = k;
        }
    }
    __syncthreads();
    int k = ictl[1];

    // ---- keep: wholesale by bucket; exact only in the straddling bucket ----
#pragma unroll
    for (int j = 0; j < CE; j++) {
        if (j < nmine) {
            float p = pv[j];
            int i = s0 + j;
            int bd = BUCKET(p);
            int start = bd ? P[bd - 1] : 0;
            int end = P[bd];
            unsigned char kp;
            if (end <= k) kp = 1;
            else if (start >= k) kp = 0;
            else {
                int r = 0;
                for (int q = start; q < end; q++) {
                    float pr = pval[q];
                    int ir = lst[q];
                    if (pr > p || (pr == p && ir < i)) r++;
                }
                kp = (start + r < k) ? 1 : 0;
            }
            g_keep[i] = kp;
        }
    }
#undef BUCKET
}

// ---------------------------------------------------------------------------
// Kernel 4: out[i] = keep[i] ? local_f[i] : 0   (row copy, float4)
// ---------------------------------------------------------------------------
__global__ void k_writeout(const float* __restrict__ lf, float* __restrict__ out) {
    int i = blockIdx.x;
    const float4* src = (const float4*)(lf + (size_t)i * DIM);
    float4* dst = (float4*)(out + (size_t)i * DIM);
    if (g_keep[i]) {
#pragma unroll
        for (int it = 0; it < 4; it++) {
            int idx = it * 256 + threadIdx.x;
            dst[idx] = src[idx];
        }
    } else {
        float4 z = make_float4(0.f, 0.f, 0.f, 0.f);
#pragma unroll
        for (int it = 0; it < 4; it++) {
            int idx = it * 256 + threadIdx.x;
            dst[idx] = z;
        }
    }
}

// ---------------------------------------------------------------------------
extern "C" void kernel_launch(void* const* d_in, const int* in_sizes, int n_in,
                              void* d_out, int out_size) {
    const float*         lf   = (const float*)d_in[0];
    const float*         emb  = (const float*)d_in[1];
    const unsigned char* mask = (const unsigned char*)d_in[2];
    const float*         gn   = (const float*)d_in[3];
    float*               out  = (float*)d_out;

    cudaFuncSetAttribute(k_topp, cudaFuncAttributeMaxDynamicSharedMemorySize, SMEM3);

    k_textnorm<<<N_TXT, 256>>>(emb, mask);
    k_buildv<<<DIM / 256, 256>>>(emb);
    k_simdot<<<N_IMG, 256>>>(lf);
    k_topp<<<1, NTH, SMEM3>>>(gn);
    k_writeout<<<N_IMG, 256>>>(lf, out);
}

// round 7
// speedup vs baseline: 2.2282x; 1.0347x over previous
#include <cuda_runtime.h>
#include <math.h>
#include <stdint.h>

#define N_IMG 4608
#define N_TXT 128
#define DIM   4096
#define NB    4096
#define NTH   1024
#define CE    5          // elements per thread in k_topp (ceil(4608/1024))

// ---- scratch (no allocations allowed) ----
__device__ float g_v[DIM];
__device__ float g_invn[N_TXT];
__device__ float g_sim[N_IMG];
__device__ unsigned char g_keep[N_IMG];

__device__ __forceinline__ void pdl_trigger() {
#if __CUDA_ARCH__ >= 900
    cudaTriggerProgrammaticLaunchCompletion();
#endif
}
__device__ __forceinline__ void pdl_wait() {
#if __CUDA_ARCH__ >= 900
    cudaGridDependencySynchronize();
#endif
}

// ---------------------------------------------------------------------------
// Kernel 1a: per-text-row inverse norm, masked (with bool-layout probe).
// ---------------------------------------------------------------------------
__global__ void k_textnorm(const float* __restrict__ emb,
                           const unsigned char* __restrict__ maskb) {
    int t = blockIdx.x;
    const float* row = emb + (size_t)t * DIM;
    float ss = 0.f;
    for (int d = threadIdx.x; d < DIM; d += blockDim.x) {
        float x = row[d];
        ss += x * x;
    }
    __shared__ float sm[8];
    for (int o = 16; o; o >>= 1) ss += __shfl_xor_sync(0xffffffffu, ss, o);
    if ((threadIdx.x & 31) == 0) sm[threadIdx.x >> 5] = ss;
    __syncthreads();
    if (threadIdx.x == 0) {
        float tot = 0.f;
        for (int w = 0; w < 8; w++) tot += sm[w];
        bool isU8 = false;
        for (int j = 1; j < N_TXT; j++) {
            if ((j & 3) != 0 && maskb[j] != 0) { isU8 = true; break; }
        }
        bool mv = isU8 ? (maskb[t] != 0) : (((const int*)maskb)[t] != 0);
        float n = fmaxf(sqrtf(tot), 1e-8f);
        g_invn[t] = mv ? (1.f / n) : 0.f;
    }
}

// ---------------------------------------------------------------------------
// Kernel 1b: v[d] = sum_t emb[t][d] * invn[t].  Triggers early so k_simdot
// (PDL) can start streaming local_f concurrently.
// ---------------------------------------------------------------------------
__global__ void k_buildv(const float* __restrict__ emb) {
    pdl_trigger();
    int d = blockIdx.x * blockDim.x + threadIdx.x;
    float acc = 0.f;
#pragma unroll 4
    for (int t = 0; t < N_TXT; t++)
        acc = fmaf(emb[(size_t)t * DIM + d], g_invn[t], acc);
    g_v[d] = acc;
}

// ---------------------------------------------------------------------------
// Kernel 2 (PDL): phase 1 = load row into registers + ||f||^2 (independent of
// v); grid-dep-sync; phase 2 = dot with g_v. Triggers early so k_topp (PDL)
// can run its prologue under our tail.
// ---------------------------------------------------------------------------
__global__ void k_simdot(const float* __restrict__ lf) {
    pdl_trigger();
    int i = blockIdx.x;
    const float4* row = (const float4*)(lf + (size_t)i * DIM);
    float4 a[4];
    float ss = 0.f;
#pragma unroll
    for (int it = 0; it < 4; it++) {
        a[it] = row[it * 256 + threadIdx.x];
        ss += a[it].x * a[it].x + a[it].y * a[it].y
            + a[it].z * a[it].z + a[it].w * a[it].w;
    }
    pdl_wait();   // g_v ready
    const float4* v4 = (const float4*)g_v;
    float dot = 0.f;
#pragma unroll
    for (int it = 0; it < 4; it++) {
        float4 b = v4[it * 256 + threadIdx.x];
        dot += a[it].x * b.x + a[it].y * b.y + a[it].z * b.z + a[it].w * b.w;
    }
    __shared__ float sd[8], sq[8];
    for (int o = 16; o; o >>= 1) {
        dot += __shfl_xor_sync(0xffffffffu, dot, o);
        ss  += __shfl_xor_sync(0xffffffffu, ss, o);
    }
    if ((threadIdx.x & 31) == 0) { sd[threadIdx.x >> 5] = dot; sq[threadIdx.x >> 5] = ss; }
    __syncthreads();
    if (threadIdx.x == 0) {
        float d = 0.f, s = 0.f;
        for (int w = 0; w < 8; w++) { d += sd[w]; s += sq[w]; }
        float n = fmaxf(sqrtf(s), 1e-8f);
        g_sim[i] = d / n;
    }
}

// ---------------------------------------------------------------------------
// Kernel 3 (PDL, 1 block): triggers at entry so k_writeout launches and copies
// concurrently. Prologue (zero tables, load gumbel) runs pre-sync.
// Shared layout (bytes):
//   pval : [0,     18432)  p values in scatter order (bucket-grouped)
//   lst  : [18432, 36864)  element ids in scatter order
//   P    : [36864, 53248)  NB ints: hist -> starts -> ends
//   S    : [53248, 86016)  NB doubles: bucket sums -> inclusive prefix
//   daux : [86016, 86272)  32 doubles
//   iaux : [86272, 86400)  32 ints
//   red  : [86400, 86656)  64 floats
//   ictl : [86656, 86664)  2 ints (bstar, k)
// ---------------------------------------------------------------------------
#define SMEM3 86720

__device__ __forceinline__ float blk_max(float v, float* red, int tid) {
    for (int o = 16; o; o >>= 1) v = fmaxf(v, __shfl_xor_sync(0xffffffffu, v, o));
    if ((tid & 31) == 0) red[tid >> 5] = v;
    __syncthreads();
    if (tid < 32) {
        float x = red[tid];
        for (int o = 16; o; o >>= 1) x = fmaxf(x, __shfl_xor_sync(0xffffffffu, x, o));
        if (tid == 0) red[0] = x;
    }
    __syncthreads();
    float r = red[0];
    __syncthreads();
    return r;
}

__device__ __forceinline__ float blk_sum(float v, float* red, int tid) {
    for (int o = 16; o; o >>= 1) v += __shfl_xor_sync(0xffffffffu, v, o);
    if ((tid & 31) == 0) red[tid >> 5] = v;
    __syncthreads();
    if (tid < 32) {
        float x = red[tid];
        for (int o = 16; o; o >>= 1) x += __shfl_xor_sync(0xffffffffu, x, o);
        if (tid == 0) red[0] = x;
    }
    __syncthreads();
    float r = red[0];
    __syncthreads();
    return r;
}

__global__ void __launch_bounds__(NTH, 1) k_topp(const float* __restrict__ gnoise) {
    pdl_trigger();   // single block: writeout may launch immediately
    extern __shared__ unsigned char sraw[];
    float*  pval = (float*)(sraw);
    int*    lst  = (int*)(sraw + 18432);
    int*    P    = (int*)(sraw + 36864);
    double* S    = (double*)(sraw + 53248);
    double* daux = (double*)(sraw + 86016);
    int*    iaux = (int*)(sraw + 86272);
    float*  red  = (float*)(sraw + 86400);
    int*    ictl = (int*)(sraw + 86656);
    int tid  = threadIdx.x;
    int lane = tid & 31;
    int w    = tid >> 5;
    int s0   = tid * CE;
    int nmine = min(CE, max(0, N_IMG - s0));

    float val[CE];
    float pv[CE];
    float gn[CE];

    // ---- prologue (independent of k_simdot): zero tables, load gumbel ----
    for (int b = tid; b < NB; b += NTH) { P[b] = 0; S[b] = 0.0; }
    if (tid == 0) ictl[0] = NB;
#pragma unroll
    for (int j = 0; j < CE; j++)
        if (j < nmine) gn[j] = gnoise[s0 + j];

    pdl_wait();   // g_sim ready

    // ---- pass 1: t = 2*sim, max -> m1 ----
    float lm = -INFINITY;
#pragma unroll
    for (int j = 0; j < CE; j++) {
        if (j < nmine) {
            float t = 2.f * g_sim[s0 + j];
            val[j] = t;
            lm = fmaxf(lm, t);
        }
    }
    float m1 = blk_max(lm, red, tid);

    // ---- pass 2: e = exp(t - m1), sum -> Z1 ----
    float lsum = 0.f;
#pragma unroll
    for (int j = 0; j < CE; j++) {
        if (j < nmine) {
            float e = expf(val[j] - m1);
            val[j] = e;
            lsum += e;
        }
    }
    float Z1 = blk_sum(lsum, red, tid);
    float r1 = 1.f / Z1;

    // ---- pass 3: z = e/Z1 + g, max -> m2 ----
    float lm2 = -INFINITY;
#pragma unroll
    for (int j = 0; j < CE; j++) {
        if (j < nmine) {
            float z = val[j] * r1 + gn[j];
            val[j] = z;
            lm2 = fmaxf(lm2, z);
        }
    }
    float m2 = blk_max(lm2, red, tid);

    // ---- pass 4: e2 = exp(z - m2); sum + min/max in one reduction ----
    float ls2 = 0.f, emin = INFINITY, emax = -INFINITY;
#pragma unroll
    for (int j = 0; j < CE; j++) {
        if (j < nmine) {
            float e = expf(val[j] - m2);
            val[j] = e;
            ls2 += e;
            emin = fminf(emin, e);
            emax = fmaxf(emax, e);
        }
    }
    for (int o = 16; o; o >>= 1) {
        ls2  += __shfl_xor_sync(0xffffffffu, ls2, o);
        emin  = fminf(emin, __shfl_xor_sync(0xffffffffu, emin, o));
        emax  = fmaxf(emax, __shfl_xor_sync(0xffffffffu, emax, o));
    }
    if (lane == 0) { red[w] = ls2; red[32 + w] = emin; daux[w] = (double)emax; }
    __syncthreads();
    if (tid < 32) {
        float a = red[tid];
        float b = red[32 + tid];
        float c = (float)daux[tid];
        for (int o = 16; o; o >>= 1) {
            a += __shfl_xor_sync(0xffffffffu, a, o);
            b  = fminf(b, __shfl_xor_sync(0xffffffffu, b, o));
            c  = fmaxf(c, __shfl_xor_sync(0xffffffffu, c, o));
        }
        if (tid == 0) { red[0] = a; red[1] = b; red[2] = c; }
    }
    __syncthreads();
    float Z2 = red[0];
    float pmin = red[1] / Z2;   // p=f32(e2/Z2) monotone in e2 -> exact min/max
    float pmax = red[2] / Z2;
    float scale = (float)(NB - 1) / fmaxf(pmax - pmin, 1e-30f);
    __syncthreads();

#define BUCKET(p) min(max((int)((pmax - (p)) * scale), 0), NB - 1)

    // ---- p = e2/Z2 (exact div, reference rounding); count + double sum ----
#pragma unroll
    for (int j = 0; j < CE; j++) {
        if (j < nmine) {
            float p = val[j] / Z2;
            pv[j] = p;
            int bd = BUCKET(p);
            atomicAdd(&P[bd], 1);
            atomicAdd(&S[bd], (double)p);
        }
    }
    __syncthreads();

    // ---- fused scans: P -> exclusive starts, S -> inclusive double prefix ----
    const int CB = NB / NTH;  // 4
    int base = tid * CB;
    int run = 0; double drun = 0.0;
#pragma unroll
    for (int j = 0; j < CB; j++) {
        int t = P[base + j];
        P[base + j] = run;
        run += t;
        drun += S[base + j];
        S[base + j] = drun;          // inclusive within chunk
    }
    int iv = run; double dv = drun;
    for (int o = 1; o < 32; o <<= 1) {
        int ti = __shfl_up_sync(0xffffffffu, iv, o);
        double td = __shfl_up_sync(0xffffffffu, dv, o);
        if (lane >= o) { iv += ti; dv += td; }
    }
    if (lane == 31) { iaux[w] = iv; daux[w] = dv; }
    __syncthreads();
    if (tid < 32) {
        int x = iaux[tid]; double y = daux[tid];
        for (int o = 1; o < 32; o <<= 1) {
            int ti = __shfl_up_sync(0xffffffffu, x, o);
            double td = __shfl_up_sync(0xffffffffu, y, o);
            if (tid >= o) { x += ti; y += td; }
        }
        iaux[tid] = x; daux[tid] = y;
    }
    __syncthreads();
    int iexcl = (iv - run) + (w ? iaux[w - 1] : 0);
    double dexcl = (dv - drun) + (w ? daux[w - 1] : 0.0);
    if (iexcl) {
#pragma unroll
        for (int j = 0; j < CB; j++) P[base + j] += iexcl;
    }
    if (dexcl != 0.0) {
#pragma unroll
        for (int j = 0; j < CB; j++) S[base + j] += dexcl;
    }
    __syncthreads();

    // ---- scatter (p, id) by bucket; P becomes bucket ends ----
#pragma unroll
    for (int j = 0; j < CE; j++) {
        if (j < nmine) {
            int bd = BUCKET(pv[j]);
            int pos = atomicAdd(&P[bd], 1);
            lst[pos] = s0 + j;
            pval[pos] = pv[j];
        }
    }
    __syncthreads();

    const double TOPPD = (double)0.9f;  // jax promotes 0.9 -> f32

    // ---- find crossing bucket b*: S[b*] > 0.9 >= S[b*-1] ----
#pragma unroll
    for (int j = 0; j < CB; j++) {
        int b = base + j;
        double incl = S[b];
        double prev = b ? S[b - 1] : 0.0;
        if (incl > TOPPD && prev <= TOPPD) atomicMin(&ictl[0], b);
    }
    __syncthreads();
    int bstar = ictl[0];

    // ---- warp 0: resolve crossing bucket element-exactly -> count, k ----
    if (w == 0) {
        int count;
        if (bstar >= NB) {
            count = N_IMG;
        } else {
            int start = bstar ? P[bstar - 1] : 0;
            int end = P[bstar];
            double pref = bstar ? S[bstar - 1] : 0.0;
            int cin = 0;
            for (int q = start + lane; q < end; q += 32) {
                float p = pval[q];
                int id = lst[q];
                double sb = 0.0;
                for (int r = start; r < end; r++) {
                    float pr = pval[r];
                    int ir = lst[r];
                    if (pr > p || (pr == p && ir <= id)) sb += (double)pr;
                }
                if (pref + sb <= TOPPD) cin++;
            }
            for (int o = 16; o; o >>= 1) cin += __shfl_xor_sync(0xffffffffu, cin, o);
            count = start + cin;
        }
        if (lane == 0) {
            int k = count + 1;
            if (k > N_IMG) k = N_IMG;
            ictl[1] = k;
        }
    }
    __syncthreads();
    int k = ictl[1];

    // ---- keep: wholesale by bucket; exact only in the straddling bucket ----
#pragma unroll
    for (int j = 0; j < CE; j++) {
        if (j < nmine) {
            float p = pv[j];
            int i = s0 + j;
            int bd = BUCKET(p);
            int start = bd ? P[bd - 1] : 0;
            int end = P[bd];
            unsigned char kp;
            if (end <= k) kp = 1;
            else if (start >= k) kp = 0;
            else {
                int r = 0;
                for (int q = start; q < end; q++) {
                    float pr = pval[q];
                    int ir = lst[q];
                    if (pr > p || (pr == p && ir < i)) r++;
                }
                kp = (start + r < k) ? 1 : 0;
            }
            g_keep[i] = kp;
        }
    }
#undef BUCKET
}

// ---------------------------------------------------------------------------
// Kernel 4 (PDL): copy ALL rows first (independent of keep, overlaps k_topp),
// then grid-dep-sync and re-zero the dropped rows (~10% of rows).
// ---------------------------------------------------------------------------
__global__ void k_writeout(const float* __restrict__ lf, float* __restrict__ out) {
    int i = blockIdx.x;
    const float4* src = (const float4*)(lf + (size_t)i * DIM);
    float4* dst = (float4*)(out + (size_t)i * DIM);
    int t = threadIdx.x;
    float4 a0 = src[t];
    float4 a1 = src[256 + t];
    float4 a2 = src[512 + t];
    float4 a3 = src[768 + t];
    dst[t]       = a0;
    dst[256 + t] = a1;
    dst[512 + t] = a2;
    dst[768 + t] = a3;
    pdl_wait();   // g_keep ready
    if (!g_keep[i]) {
        float4 z = make_float4(0.f, 0.f, 0.f, 0.f);
        dst[t]       = z;
        dst[256 + t] = z;
        dst[512 + t] = z;
        dst[768 + t] = z;
    }
}

// ---------------------------------------------------------------------------
extern "C" void kernel_launch(void* const* d_in, const int* in_sizes, int n_in,
                              void* d_out, int out_size) {
    const float*         lf   = (const float*)d_in[0];
    const float*         emb  = (const float*)d_in[1];
    const unsigned char* mask = (const unsigned char*)d_in[2];
    const float*         gn   = (const float*)d_in[3];
    float*               out  = (float*)d_out;

    cudaFuncSetAttribute(k_topp, cudaFuncAttributeMaxDynamicSharedMemorySize, SMEM3);

    k_textnorm<<<N_TXT, 256>>>(emb, mask);
    k_buildv<<<DIM / 256, 256>>>(emb);

    cudaLaunchAttribute pdl[1];
    pdl[0].id = cudaLaunchAttributeProgrammaticStreamSerialization;
    pdl[0].val.programmaticStreamSerializationAllowed = 1;

    {   // k_simdot: overlap row loads with k_buildv
        cudaLaunchConfig_t cfg = {};
        cfg.gridDim = dim3(N_IMG, 1, 1);
        cfg.blockDim = dim3(256, 1, 1);
        cfg.attrs = pdl;
        cfg.numAttrs = 1;
        cudaLaunchKernelEx(&cfg, k_simdot, lf);
    }
    {   // k_topp: prologue overlaps k_simdot tail
        cudaLaunchConfig_t cfg = {};
        cfg.gridDim = dim3(1, 1, 1);
        cfg.blockDim = dim3(NTH, 1, 1);
        cfg.dynamicSmemBytes = SMEM3;
        cfg.attrs = pdl;
        cfg.numAttrs = 1;
        cudaLaunchKernelEx(&cfg, k_topp, gn);
    }
    {   // k_writeout: bulk copy overlaps k_topp entirely
        cudaLaunchConfig_t cfg = {};
        cfg.gridDim = dim3(N_IMG, 1, 1);
        cfg.blockDim = dim3(256, 1, 1);
        cfg.attrs = pdl;
        cfg.numAttrs = 1;
        cudaLaunchKernelEx(&cfg, k_writeout, lf, out);
    }
}